// round 13
// baseline (speedup 1.0000x reference)
#include <cuda_runtime.h>
#include <cuda_bf16.h>

#define N_BODIES 512
#define HID 128
#define IN_DIM 7
#define OUT_DIM (N_BODIES * 6)      // 3072
#define KDIM (N_BODIES * HID)       // 65536
#define NEG_SLOPE 0.2f
#define KSPLITS 256                  // 256 K-rows per split

// W_fc in float4 units: 50,331,648 total. Preload last 32 splits (96 MB).
#define W4_TOTAL   50331648ull
#define H2_PF_OFF  44040192ull      // split 224 start
#define H2_PF_IT   96               // 64 blk x 256 thr x 96 = 1,572,864 f4 (24 MB)
#define XH_PF_OFF  45613056ull
#define XH_PF_IT   64               // 64 blk x 512 thr x 64 = 2,097,152 f4 (32 MB)
#define GAT_PF_OFF 47710208ull
#define GAT_PF_IT  107              // 96 blk x 256 thr, guarded (40 MB)

// ---- scratch (no allocations allowed) ----
__device__ float g_h1[N_BODIES * HID];
__device__ float g_p1[128 * HID];        // per-block column sums of h1
__device__ float g_h2[N_BODIES * HID];
__device__ float g_xh[N_BODIES * 2 * HID];   // GAT projected features [N,256]
__device__ float g_as[N_BODIES * 2];
__device__ float g_ad[N_BODIES * 2];
__device__ float g_hp[4 * KDIM];         // GAT partials: [jhalf*2+head][node][col]
__device__ float g_part[KSPLITS * OUT_DIM];  // 3 MB matvec partials
__device__ float g_sink[4];              // keeps preload loads alive (never written)

// ============================================================
// K1: h1 = relu(c1 + x@Wc1) + per-block column sums. 128 blocks x 4 rows, 128 thr.
__global__ void __launch_bounds__(128) k_h1(const float* __restrict__ x,
                      const float* __restrict__ W_res, const float* __restrict__ b_res,
                      const float* __restrict__ W_rel1, const float* __restrict__ b_rel1,
                      const float* __restrict__ W_root1) {
    __shared__ float sSx[4][IN_DIM];
    __shared__ float sx[4][IN_DIM];
    int c = threadIdx.x;
    int w = c >> 5, lane = c & 31;
    int r0 = blockIdx.x * 4;
    {
        float p[IN_DIM];
        #pragma unroll
        for (int d = 0; d < IN_DIM; d++) p[d] = 0.f;
        #pragma unroll
        for (int q = 0; q < 4; q++) {
            const float* xr = x + (c + q * 128) * IN_DIM;
            #pragma unroll
            for (int d = 0; d < IN_DIM; d++) p[d] += xr[d];
        }
        #pragma unroll
        for (int d = 0; d < IN_DIM; d++) {
            float v = p[d];
            #pragma unroll
            for (int o = 16; o; o >>= 1) v += __shfl_xor_sync(0xffffffffu, v, o);
            if (lane == 0) sSx[w][d] = v;
        }
    }
    if (c < 4 * IN_DIM) sx[c / IN_DIM][c % IN_DIM] = x[r0 * IN_DIM + c];
    __syncthreads();
    float Sx[IN_DIM];
    #pragma unroll
    for (int d = 0; d < IN_DIM; d++)
        Sx[d] = sSx[0][d] + sSx[1][d] + sSx[2][d] + sSx[3][d];
    float base = b_rel1[c] + b_res[c];
    float wc[IN_DIM];
    #pragma unroll
    for (int d = 0; d < IN_DIM; d++) {
        float rel = W_rel1[d * HID + c];
        base += Sx[d] * rel;
        wc[d] = W_root1[d * HID + c] + W_res[d * HID + c] - rel;
    }
    float colsum = 0.f;
    #pragma unroll
    for (int r = 0; r < 4; r++) {
        float acc = base;
        #pragma unroll
        for (int d = 0; d < IN_DIM; d++) acc += sx[r][d] * wc[d];
        acc = fmaxf(acc, 0.f);
        g_h1[(r0 + r) * HID + c] = acc;
        colsum += acc;
    }
    g_p1[blockIdx.x * HID + c] = colsum;
}

// K2: h2 GEMM (blocks 0..127) + W_fc L2 preload (blocks 128..191). 256 threads.
__global__ void __launch_bounds__(256) k_h2(const float* __restrict__ W_rel2,
                                            const float* __restrict__ W_root2,
                                            const float* __restrict__ b_rel2,
                                            const float* __restrict__ Wfc) {
    if (blockIdx.x >= 128) {
        int pb = blockIdx.x - 128;
        const float4* W4 = (const float4*)Wfc;
        size_t idx = H2_PF_OFF + (size_t)pb * 256 + threadIdx.x;
        float s = 0.f;
        #pragma unroll 8
        for (int k = 0; k < H2_PF_IT; k++) {
            float4 p = W4[idx + (size_t)k * (64 * 256)];
            s += p.x + p.y + p.z + p.w;
        }
        if (s == -1.2345678e30f) g_sink[0] = s;
        return;
    }
    __shared__ float sh[4][HID];
    __shared__ float sWrel[32][HID];
    __shared__ float sWd[32][HID];
    __shared__ float red[2][HID];
    __shared__ float S1[HID];
    __shared__ float sc2[HID];
    int t = threadIdx.x;
    int r0 = blockIdx.x * 4;
    {
        const float4* src = (const float4*)(g_h1 + r0 * HID);
        if (t < 128) ((float4*)(&sh[0][0]))[t] = src[t];
    }
    {
        int c = t & 127, half = t >> 7;
        float s = 0.f;
        int p0 = half * 64;
        #pragma unroll 8
        for (int p = 0; p < 64; p++) s += g_p1[(p0 + p) * HID + c];
        red[half][c] = s;
    }
    __syncthreads();
    if (t < HID) S1[t] = red[0][t] + red[1][t];
    __syncthreads();
    int c = t & 127, rg = (t >> 7) * 2;     // 2 rows per thread
    float a0 = 0.f, a1 = 0.f;
    float c2acc = 0.f;
    #pragma unroll
    for (int s = 0; s < 4; s++) {
        __syncthreads();
        {
            const float4* rsrc = (const float4*)(W_rel2 + s * 32 * HID);
            const float4* osrc = (const float4*)(W_root2 + s * 32 * HID);
            float4* rdst = (float4*)(&sWrel[0][0]);
            float4* ddst = (float4*)(&sWd[0][0]);
            #pragma unroll
            for (int q = 0; q < 4; q++) {
                float4 rv = rsrc[t + q * 256];
                float4 ov = osrc[t + q * 256];
                rdst[t + q * 256] = rv;
                float4 dv = {ov.x - rv.x, ov.y - rv.y, ov.z - rv.z, ov.w - rv.w};
                ddst[t + q * 256] = dv;
            }
        }
        __syncthreads();
        #pragma unroll
        for (int d = 0; d < 32; d++) {
            float w = sWd[d][c];
            int dd = s * 32 + d;
            a0 += sh[rg + 0][dd] * w;
            a1 += sh[rg + 1][dd] * w;
        }
        if (t < HID) {
            #pragma unroll
            for (int d = 0; d < 32; d++) c2acc += S1[s * 32 + d] * sWrel[d][t];
        }
    }
    if (t < HID) sc2[t] = c2acc + b_rel2[t];
    __syncthreads();
    float base = sc2[c];
    g_h2[(r0 + rg + 0) * HID + c] = fmaxf(a0 + base, 0.f);
    g_h2[(r0 + rg + 1) * HID + c] = fmaxf(a1 + base, 0.f);
}

// K3: xh GEMM + logits (blocks 0..127) + preload (blocks 128..191). 512 threads.
__global__ void __launch_bounds__(512) k_xh(const float* __restrict__ W_gat,
                                            const float* __restrict__ att_src,
                                            const float* __restrict__ att_dst,
                                            const float* __restrict__ Wfc) {
    if (blockIdx.x >= 128) {
        int pb = blockIdx.x - 128;
        const float4* W4 = (const float4*)Wfc;
        size_t idx = XH_PF_OFF + (size_t)pb * 512 + threadIdx.x;
        float s = 0.f;
        #pragma unroll 8
        for (int k = 0; k < XH_PF_IT; k++) {
            float4 p = W4[idx + (size_t)k * (64 * 512)];
            s += p.x + p.y + p.z + p.w;
        }
        if (s == -1.2345678e30f) g_sink[1] = s;
        return;
    }
    __shared__ float sh[4][HID];
    __shared__ float sW[32][256];
    __shared__ float sxh[4][256];
    int r0 = blockIdx.x * 4;
    int t = threadIdx.x;
    {
        const float4* src = (const float4*)(g_h2 + r0 * HID);
        if (t < 128) ((float4*)(&sh[0][0]))[t] = src[t];
    }
    int c = t & 255, rg = (t >> 8) * 2;     // 2 rows per thread
    float a0 = 0.f, a1 = 0.f;
    #pragma unroll
    for (int s = 0; s < 4; s++) {
        __syncthreads();
        {
            const float4* wsrc = (const float4*)(W_gat + s * 32 * 256);
            float4* wdst = (float4*)(&sW[0][0]);
            #pragma unroll
            for (int q = 0; q < 4; q++) wdst[t + q * 512] = wsrc[t + q * 512];
        }
        __syncthreads();
        #pragma unroll
        for (int d = 0; d < 32; d++) {
            float w = sW[d][c];
            int dd = s * 32 + d;
            a0 += sh[rg + 0][dd] * w;
            a1 += sh[rg + 1][dd] * w;
        }
    }
    g_xh[(r0 + rg + 0) * 256 + c] = a0;  sxh[rg + 0][c] = a0;
    g_xh[(r0 + rg + 1) * 256 + c] = a1;  sxh[rg + 1][c] = a1;
    __syncthreads();
    // logits: 8 pairs (4 rows x 2 heads), warps 0..7
    int w = t >> 5, lane = t & 31;
    if (w < 8) {
        int row = w >> 1, h = w & 1;
        float ds = 0.f, dd2 = 0.f;
        #pragma unroll
        for (int q = 0; q < 4; q++) {
            int cc = lane + q * 32;
            float v = sxh[row][h * 128 + cc];
            ds += v * att_src[h * HID + cc];
            dd2 += v * att_dst[h * HID + cc];
        }
        #pragma unroll
        for (int o = 16; o; o >>= 1) {
            ds += __shfl_xor_sync(0xffffffffu, ds, o);
            dd2 += __shfl_xor_sync(0xffffffffu, dd2, o);
        }
        if (lane == 0) {
            g_as[(r0 + row) * 2 + h] = ds;
            g_ad[(r0 + row) * 2 + h] = dd2;
        }
    }
}

// K4: GAT aggregation (blocks 0..255, R8-proven) + preload (blocks 256..351).
__global__ void __launch_bounds__(256) k_gat(const float* __restrict__ Wfc) {
    if (blockIdx.x >= 256) {
        int pb = blockIdx.x - 256;
        const float4* W4 = (const float4*)Wfc;
        size_t idx = GAT_PF_OFF + (size_t)pb * 256 + threadIdx.x;
        float s = 0.f;
        #pragma unroll 8
        for (int k = 0; k < GAT_PF_IT; k++) {
            size_t i = idx + (size_t)k * (96 * 256);
            if (i < W4_TOTAL) {
                float4 p = W4[i];
                s += p.x + p.y + p.z + p.w;
            }
        }
        if (s == -1.2345678e30f) g_sink[2] = s;
        return;
    }
    __shared__ float al[8 * 256];     // alpha[d][jloc] for this (head, j-half), 8 KB
    __shared__ float sred[4 * 1024];  // reduction buffer, 16 KB
    int jh = blockIdx.x & 1;
    int h  = (blockIdx.x >> 1) & 1;
    int i0 = (blockIdx.x >> 2) * 8;
    int t = threadIdx.x;
    int w = t >> 5, lane = t & 31;

    // phase 1: warp w -> softmax stats over ALL 512 j, store only our half
    {
        float ad = g_ad[(i0 + w) * 2 + h];
        float ev[16];
        float m = -1e30f;
        #pragma unroll
        for (int q = 0; q < 16; q++) {
            int j = lane + q * 32;
            float tv = g_as[j * 2 + h] + ad;
            float e = tv > 0.f ? tv : NEG_SLOPE * tv;
            ev[q] = e;
            m = fmaxf(m, e);
        }
        #pragma unroll
        for (int o = 16; o; o >>= 1) m = fmaxf(m, __shfl_xor_sync(0xffffffffu, m, o));
        float z = 0.f;
        #pragma unroll
        for (int q = 0; q < 16; q++) { float wv = __expf(ev[q] - m); ev[q] = wv; z += wv; }
        #pragma unroll
        for (int o = 16; o; o >>= 1) z += __shfl_xor_sync(0xffffffffu, z, o);
        float inv = 1.f / z;
        int q0 = jh * 8;
        #pragma unroll
        for (int qq = 0; qq < 8; qq++)
            al[w * 256 + lane + qq * 32] = ev[q0 + qq] * inv;
    }
    __syncthreads();

    // phase 2: thread = (col-quad cq, j-group jg of 32 j). 4 cols x 8 dst accums.
    int cq = t & 31, jg = t >> 5;
    const float4* X4 = (const float4*)(g_xh + h * 128 + cq * 4);  // index j*64
    const float4* AL4 = (const float4*)al;          // [d*64 + jloc/4]
    float4 acc[8];
    #pragma unroll
    for (int d = 0; d < 8; d++) acc[d] = make_float4(0.f, 0.f, 0.f, 0.f);
    int jbase = jh * 256 + jg * 32;
    int jlbase = jg * 32;
    #pragma unroll 2
    for (int jq = 0; jq < 8; jq++) {
        int j = jbase + jq * 4;
        int jl4 = (jlbase >> 2) + jq;
        float4 x0 = X4[(size_t)(j + 0) * 64];
        float4 x1 = X4[(size_t)(j + 1) * 64];
        float4 x2 = X4[(size_t)(j + 2) * 64];
        float4 x3 = X4[(size_t)(j + 3) * 64];
        #pragma unroll
        for (int d = 0; d < 8; d++) {
            float4 a = AL4[d * 64 + jl4];          // warp-uniform broadcast
            acc[d].x += a.x * x0.x + a.y * x1.x + a.z * x2.x + a.w * x3.x;
            acc[d].y += a.x * x0.y + a.y * x1.y + a.z * x2.y + a.w * x3.y;
            acc[d].z += a.x * x0.z + a.y * x1.z + a.z * x2.z + a.w * x3.z;
            acc[d].w += a.x * x0.w + a.y * x1.w + a.z * x2.w + a.w * x3.w;
        }
    }
    // two-round deterministic reduction over 8 j-groups
    float4* S4 = (float4*)sred;
    if (jg < 4) {
        #pragma unroll
        for (int d = 0; d < 8; d++) S4[jg * 256 + d * 32 + cq] = acc[d];
    }
    __syncthreads();
    if (jg >= 4) {
        #pragma unroll
        for (int d = 0; d < 8; d++) {
            float4 v = S4[(jg - 4) * 256 + d * 32 + cq];
            v.x += acc[d].x; v.y += acc[d].y; v.z += acc[d].z; v.w += acc[d].w;
            S4[(jg - 4) * 256 + d * 32 + cq] = v;
        }
    }
    __syncthreads();
    {
        float4 v = S4[t];
        #pragma unroll
        for (int g = 1; g < 4; g++) {
            float4 u = S4[g * 256 + t];
            v.x += u.x; v.y += u.y; v.z += u.z; v.w += u.w;
        }
        int d = t >> 5, cc0 = (t & 31) * 4;
        ((float4*)(g_hp + ((size_t)(jh * 2 + h)) * KDIM
                         + (size_t)(i0 + d) * HID + cc0))[0] = v;
    }
}

// K5: split-K matvec; folds GAT half/head-combine + bias + relu into v load.
__global__ void __launch_bounds__(768) k_matvec(const float* __restrict__ Wfc,
                                                const float* __restrict__ b_gat) {
    int b = blockIdx.x, t = threadIdx.x;
    __shared__ float v[256];
    int k0 = b * 256;
    if (t < 256) {
        int k = k0 + t;
        float hv = 0.5f * ((g_hp[k] + g_hp[2 * KDIM + k])          // head 0
                         + (g_hp[KDIM + k] + g_hp[3 * KDIM + k]))  // head 1
                 + b_gat[t & 127];
        v[t] = fmaxf(hv, 0.f);
    }
    __syncthreads();
    const float4* W4 = (const float4*)Wfc;     // row = 768 float4
    size_t base = (size_t)k0 * 768 + t;
    float4 s0 = {0,0,0,0}, s1 = {0,0,0,0}, s2 = {0,0,0,0}, s3 = {0,0,0,0};
    #pragma unroll 2
    for (int kk = 0; kk < 256; kk += 8) {
        float4 w0 = __ldcs(&W4[base + (size_t)(kk + 0) * 768]);
        float4 w1 = __ldcs(&W4[base + (size_t)(kk + 1) * 768]);
        float4 w2 = __ldcs(&W4[base + (size_t)(kk + 2) * 768]);
        float4 w3 = __ldcs(&W4[base + (size_t)(kk + 3) * 768]);
        float4 w4 = __ldcs(&W4[base + (size_t)(kk + 4) * 768]);
        float4 w5 = __ldcs(&W4[base + (size_t)(kk + 5) * 768]);
        float4 w6 = __ldcs(&W4[base + (size_t)(kk + 6) * 768]);
        float4 w7 = __ldcs(&W4[base + (size_t)(kk + 7) * 768]);
        float v0 = v[kk], v1 = v[kk + 1], v2 = v[kk + 2], v3 = v[kk + 3];
        float v4 = v[kk + 4], v5 = v[kk + 5], v6 = v[kk + 6], v7 = v[kk + 7];
        s0.x += v0 * w0.x; s0.y += v0 * w0.y; s0.z += v0 * w0.z; s0.w += v0 * w0.w;
        s1.x += v1 * w1.x; s1.y += v1 * w1.y; s1.z += v1 * w1.z; s1.w += v1 * w1.w;
        s2.x += v2 * w2.x; s2.y += v2 * w2.y; s2.z += v2 * w2.z; s2.w += v2 * w2.w;
        s3.x += v3 * w3.x; s3.y += v3 * w3.y; s3.z += v3 * w3.z; s3.w += v3 * w3.w;
        s0.x += v4 * w4.x; s0.y += v4 * w4.y; s0.z += v4 * w4.z; s0.w += v4 * w4.w;
        s1.x += v5 * w5.x; s1.y += v5 * w5.y; s1.z += v5 * w5.z; s1.w += v5 * w5.w;
        s2.x += v6 * w6.x; s2.y += v6 * w6.y; s2.z += v6 * w6.z; s2.w += v6 * w6.w;
        s3.x += v7 * w7.x; s3.y += v7 * w7.y; s3.z += v7 * w7.z; s3.w += v7 * w7.w;
    }
    float4 r;
    r.x = s0.x + s1.x + s2.x + s3.x;
    r.y = s0.y + s1.y + s2.y + s3.y;
    r.z = s0.z + s1.z + s2.z + s3.z;
    r.w = s0.w + s1.w + s2.w + s3.w;
    ((float4*)g_part)[(size_t)b * 768 + t] = r;
}

// K6: fused reduction: 256 partials -> out, one kernel. 12 blocks x 1024.
__global__ void __launch_bounds__(1024) k_reduce(const float* __restrict__ b_fc,
                                                 float* __restrict__ out) {
    __shared__ float s[1024];
    int t = threadIdx.x;
    int o_local = t & 255, chunk = t >> 8;     // 4 chunks of 64 splits
    int o = blockIdx.x * 256 + o_local;
    float acc = 0.f;
    int s0 = chunk * 64;
    #pragma unroll 8
    for (int p = 0; p < 64; p++) acc += g_part[(size_t)(s0 + p) * OUT_DIM + o];
    s[t] = acc;
    __syncthreads();
    if (t < 256) {
        out[blockIdx.x * 256 + t] = b_fc[blockIdx.x * 256 + t]
            + ((s[t] + s[256 + t]) + (s[512 + t] + s[768 + t]));
    }
}

extern "C" void kernel_launch(void* const* d_in, const int* in_sizes, int n_in,
                              void* d_out, int out_size) {
    const float* x       = (const float*)d_in[0];
    // d_in[1] = edge_index (fully connected by construction)
    const float* W_res   = (const float*)d_in[2];
    const float* b_res   = (const float*)d_in[3];
    const float* W_rel1  = (const float*)d_in[4];
    const float* b_rel1  = (const float*)d_in[5];
    const float* W_root1 = (const float*)d_in[6];
    const float* W_rel2  = (const float*)d_in[7];
    const float* b_rel2  = (const float*)d_in[8];
    const float* W_root2 = (const float*)d_in[9];
    const float* W_gat   = (const float*)d_in[10];
    const float* att_src = (const float*)d_in[11];
    const float* att_dst = (const float*)d_in[12];
    const float* b_gat   = (const float*)d_in[13];
    const float* W_fc    = (const float*)d_in[14];
    const float* b_fc    = (const float*)d_in[15];
    float* out = (float*)d_out;

    k_h1<<<128, 128>>>(x, W_res, b_res, W_rel1, b_rel1, W_root1);
    k_h2<<<192, 256>>>(W_rel2, W_root2, b_rel2, W_fc);
    k_xh<<<192, 512>>>(W_gat, att_src, att_dst, W_fc);
    k_gat<<<352, 256>>>(W_fc);
    k_matvec<<<KSPLITS, 768>>>(W_fc, b_gat);
    k_reduce<<<12, 1024>>>(b_fc, out);
}

// round 14
// speedup vs baseline: 1.1779x; 1.1779x over previous
#include <cuda_runtime.h>
#include <cuda_bf16.h>

#define N_BODIES 512
#define HID 128
#define IN_DIM 7
#define OUT_DIM (N_BODIES * 6)      // 3072
#define KDIM (N_BODIES * HID)       // 65536
#define NEG_SLOPE 0.2f
#define KSPLITS 256                  // 256 K-rows per split

// ---- scratch (no allocations allowed) ----
__device__ float g_h1[N_BODIES * HID];
__device__ float g_p1[128 * HID];        // per-block column sums of h1
__device__ float g_xh[N_BODIES * 2 * HID];   // GAT projected features [N,256]
__device__ float g_as[N_BODIES * 2];
__device__ float g_ad[N_BODIES * 2];
__device__ float g_hp[4 * KDIM];         // GAT partials: [jhalf*2+head][node][col]
__device__ float g_part[KSPLITS * OUT_DIM];  // 3 MB matvec partials

// ============================================================
// K1: h1 = relu(c1 + x@Wc1) + per-block column sums. 128 blocks x 4 rows, 128 thr.
__global__ void __launch_bounds__(128) k_h1(const float* __restrict__ x,
                      const float* __restrict__ W_res, const float* __restrict__ b_res,
                      const float* __restrict__ W_rel1, const float* __restrict__ b_rel1,
                      const float* __restrict__ W_root1) {
    __shared__ float sSx[4][IN_DIM];
    __shared__ float sx[4][IN_DIM];
    int c = threadIdx.x;
    int w = c >> 5, lane = c & 31;
    int r0 = blockIdx.x * 4;
    {
        float p[IN_DIM];
        #pragma unroll
        for (int d = 0; d < IN_DIM; d++) p[d] = 0.f;
        #pragma unroll
        for (int q = 0; q < 4; q++) {
            const float* xr = x + (c + q * 128) * IN_DIM;
            #pragma unroll
            for (int d = 0; d < IN_DIM; d++) p[d] += xr[d];
        }
        #pragma unroll
        for (int d = 0; d < IN_DIM; d++) {
            float v = p[d];
            #pragma unroll
            for (int o = 16; o; o >>= 1) v += __shfl_xor_sync(0xffffffffu, v, o);
            if (lane == 0) sSx[w][d] = v;
        }
    }
    if (c < 4 * IN_DIM) sx[c / IN_DIM][c % IN_DIM] = x[r0 * IN_DIM + c];
    __syncthreads();
    float Sx[IN_DIM];
    #pragma unroll
    for (int d = 0; d < IN_DIM; d++)
        Sx[d] = sSx[0][d] + sSx[1][d] + sSx[2][d] + sSx[3][d];
    float base = b_rel1[c] + b_res[c];
    float wc[IN_DIM];
    #pragma unroll
    for (int d = 0; d < IN_DIM; d++) {
        float rel = W_rel1[d * HID + c];
        base += Sx[d] * rel;
        wc[d] = W_root1[d * HID + c] + W_res[d * HID + c] - rel;
    }
    float colsum = 0.f;
    #pragma unroll
    for (int r = 0; r < 4; r++) {
        float acc = base;
        #pragma unroll
        for (int d = 0; d < IN_DIM; d++) acc += sx[r][d] * wc[d];
        acc = fmaxf(acc, 0.f);
        g_h1[(r0 + r) * HID + c] = acc;
        colsum += acc;
    }
    g_p1[blockIdx.x * HID + c] = colsum;
}

// K2: FUSED h2 + xh + logits. 128 blocks x 4 rows, 512 threads.
//   Phase A: h2 = relu(c2 + h1@(W_root2-W_rel2)) -> shared only (no global h2)
//   Phase B: xh = h2 @ W_gat, logits a_s/a_d
//   buf (32 KB) holds sWrel+sWd in phase A, sWgat in phase B.
__global__ void __launch_bounds__(512) k_h2xh(const float* __restrict__ W_rel2,
                                              const float* __restrict__ W_root2,
                                              const float* __restrict__ b_rel2,
                                              const float* __restrict__ W_gat,
                                              const float* __restrict__ att_src,
                                              const float* __restrict__ att_dst) {
    __shared__ float sh1[4][HID];     // 2 KB
    __shared__ float sh2[4][HID];     // 2 KB
    __shared__ float sxh[4][256];     // 4 KB
    __shared__ float red[4][HID];     // 2 KB
    __shared__ float S1[HID];
    __shared__ float sc2[HID];
    __shared__ float buf[32 * 256];   // 32 KB shared staging
    int t = threadIdx.x;
    int r0 = blockIdx.x * 4;

    // load h1 tile (4x128 = 128 float4)
    {
        const float4* src = (const float4*)(g_h1 + r0 * HID);
        if (t < 128) ((float4*)(&sh1[0][0]))[t] = src[t];
    }
    // S1 = column sums of h1 from 128 partials (4 quarters of 32)
    {
        int c = t & 127, qr = t >> 7;
        float s = 0.f;
        int p0 = qr * 32;
        #pragma unroll 8
        for (int p = 0; p < 32; p++) s += g_p1[(p0 + p) * HID + c];
        red[qr][c] = s;
    }
    __syncthreads();
    if (t < HID) S1[t] = (red[0][t] + red[1][t]) + (red[2][t] + red[3][t]);
    __syncthreads();

    // ---- Phase A: h2 GEMM ----
    float* sWrel = buf;               // [32][128]
    float* sWd   = buf + 32 * HID;    // [32][128]
    int cA = t & 127, rA = t >> 7;    // one row per thread (4 rows x 128 cols)
    float aacc = 0.f;
    float c2acc = 0.f;
    #pragma unroll
    for (int s = 0; s < 4; s++) {
        __syncthreads();
        {   // stage 32x128 rel + diff: 1024 float4 each; 512 threads x 2
            const float4* rsrc = (const float4*)(W_rel2 + s * 32 * HID);
            const float4* osrc = (const float4*)(W_root2 + s * 32 * HID);
            float4* rdst = (float4*)sWrel;
            float4* ddst = (float4*)sWd;
            #pragma unroll
            for (int q = 0; q < 2; q++) {
                int idx = t + q * 512;
                float4 rv = rsrc[idx];
                float4 ov = osrc[idx];
                rdst[idx] = rv;
                float4 dv = {ov.x - rv.x, ov.y - rv.y, ov.z - rv.z, ov.w - rv.w};
                ddst[idx] = dv;
            }
        }
        __syncthreads();
        #pragma unroll
        for (int d = 0; d < 32; d++) {
            int dd = s * 32 + d;
            aacc += sh1[rA][dd] * sWd[d * HID + cA];
        }
        if (t < HID) {
            #pragma unroll
            for (int d = 0; d < 32; d++) c2acc += S1[s * 32 + d] * sWrel[d * HID + t];
        }
    }
    if (t < HID) sc2[t] = c2acc + b_rel2[t];
    __syncthreads();
    sh2[rA][cA] = fmaxf(aacc + sc2[cA], 0.f);
    __syncthreads();

    // ---- Phase B: xh GEMM + logits ----
    float* sWg = buf;                 // [32][256]
    int cB = t & 255, rgB = (t >> 8) * 2;   // 2 rows per thread
    float b0 = 0.f, b1 = 0.f;
    #pragma unroll
    for (int s = 0; s < 4; s++) {
        __syncthreads();
        {   // stage 32x256 W_gat: 2048 float4; 512 threads x 4
            const float4* wsrc = (const float4*)(W_gat + s * 32 * 256);
            float4* wdst = (float4*)sWg;
            #pragma unroll
            for (int q = 0; q < 4; q++) wdst[t + q * 512] = wsrc[t + q * 512];
        }
        __syncthreads();
        #pragma unroll
        for (int d = 0; d < 32; d++) {
            float w = sWg[d * 256 + cB];
            int dd = s * 32 + d;
            b0 += sh2[rgB + 0][dd] * w;
            b1 += sh2[rgB + 1][dd] * w;
        }
    }
    g_xh[(r0 + rgB + 0) * 256 + cB] = b0;  sxh[rgB + 0][cB] = b0;
    g_xh[(r0 + rgB + 1) * 256 + cB] = b1;  sxh[rgB + 1][cB] = b1;
    __syncthreads();
    // logits: 8 pairs (4 rows x 2 heads), warps 0..7
    int w = t >> 5, lane = t & 31;
    if (w < 8) {
        int row = w >> 1, h = w & 1;
        float ds = 0.f, dd2 = 0.f;
        #pragma unroll
        for (int q = 0; q < 4; q++) {
            int cc = lane + q * 32;
            float v = sxh[row][h * 128 + cc];
            ds += v * att_src[h * HID + cc];
            dd2 += v * att_dst[h * HID + cc];
        }
        #pragma unroll
        for (int o = 16; o; o >>= 1) {
            ds += __shfl_xor_sync(0xffffffffu, ds, o);
            dd2 += __shfl_xor_sync(0xffffffffu, dd2, o);
        }
        if (lane == 0) {
            g_as[(r0 + row) * 2 + h] = ds;
            g_ad[(r0 + row) * 2 + h] = dd2;
        }
    }
}

// K3: GAT aggregation (R8-proven). 256 blocks: (dst-group of 8) x head x j-half.
__global__ void __launch_bounds__(256) k_gat() {
    __shared__ float al[8 * 256];     // alpha[d][jloc] for this (head, j-half), 8 KB
    __shared__ float sred[4 * 1024];  // reduction buffer, 16 KB
    int jh = blockIdx.x & 1;
    int h  = (blockIdx.x >> 1) & 1;
    int i0 = (blockIdx.x >> 2) * 8;
    int t = threadIdx.x;
    int w = t >> 5, lane = t & 31;

    // phase 1: warp w -> softmax stats over ALL 512 j, store only our half
    {
        float ad = g_ad[(i0 + w) * 2 + h];
        float ev[16];
        float m = -1e30f;
        #pragma unroll
        for (int q = 0; q < 16; q++) {
            int j = lane + q * 32;
            float tv = g_as[j * 2 + h] + ad;
            float e = tv > 0.f ? tv : NEG_SLOPE * tv;
            ev[q] = e;
            m = fmaxf(m, e);
        }
        #pragma unroll
        for (int o = 16; o; o >>= 1) m = fmaxf(m, __shfl_xor_sync(0xffffffffu, m, o));
        float z = 0.f;
        #pragma unroll
        for (int q = 0; q < 16; q++) { float wv = __expf(ev[q] - m); ev[q] = wv; z += wv; }
        #pragma unroll
        for (int o = 16; o; o >>= 1) z += __shfl_xor_sync(0xffffffffu, z, o);
        float inv = 1.f / z;
        int q0 = jh * 8;
        #pragma unroll
        for (int qq = 0; qq < 8; qq++)
            al[w * 256 + lane + qq * 32] = ev[q0 + qq] * inv;
    }
    __syncthreads();

    // phase 2: thread = (col-quad cq, j-group jg of 32 j). 4 cols x 8 dst accums.
    int cq = t & 31, jg = t >> 5;
    const float4* X4 = (const float4*)(g_xh + h * 128 + cq * 4);  // index j*64
    const float4* AL4 = (const float4*)al;          // [d*64 + jloc/4]
    float4 acc[8];
    #pragma unroll
    for (int d = 0; d < 8; d++) acc[d] = make_float4(0.f, 0.f, 0.f, 0.f);
    int jbase = jh * 256 + jg * 32;
    int jlbase = jg * 32;
    #pragma unroll 2
    for (int jq = 0; jq < 8; jq++) {
        int j = jbase + jq * 4;
        int jl4 = (jlbase >> 2) + jq;
        float4 x0 = X4[(size_t)(j + 0) * 64];
        float4 x1 = X4[(size_t)(j + 1) * 64];
        float4 x2 = X4[(size_t)(j + 2) * 64];
        float4 x3 = X4[(size_t)(j + 3) * 64];
        #pragma unroll
        for (int d = 0; d < 8; d++) {
            float4 a = AL4[d * 64 + jl4];          // warp-uniform broadcast
            acc[d].x += a.x * x0.x + a.y * x1.x + a.z * x2.x + a.w * x3.x;
            acc[d].y += a.x * x0.y + a.y * x1.y + a.z * x2.y + a.w * x3.y;
            acc[d].z += a.x * x0.z + a.y * x1.z + a.z * x2.z + a.w * x3.z;
            acc[d].w += a.x * x0.w + a.y * x1.w + a.z * x2.w + a.w * x3.w;
        }
    }
    // two-round deterministic reduction over 8 j-groups
    float4* S4 = (float4*)sred;
    if (jg < 4) {
        #pragma unroll
        for (int d = 0; d < 8; d++) S4[jg * 256 + d * 32 + cq] = acc[d];
    }
    __syncthreads();
    if (jg >= 4) {
        #pragma unroll
        for (int d = 0; d < 8; d++) {
            float4 v = S4[(jg - 4) * 256 + d * 32 + cq];
            v.x += acc[d].x; v.y += acc[d].y; v.z += acc[d].z; v.w += acc[d].w;
            S4[(jg - 4) * 256 + d * 32 + cq] = v;
        }
    }
    __syncthreads();
    {
        float4 v = S4[t];
        #pragma unroll
        for (int g = 1; g < 4; g++) {
            float4 u = S4[g * 256 + t];
            v.x += u.x; v.y += u.y; v.z += u.z; v.w += u.w;
        }
        int d = t >> 5, cc0 = (t & 31) * 4;
        ((float4*)(g_hp + ((size_t)(jh * 2 + h)) * KDIM
                         + (size_t)(i0 + d) * HID + cc0))[0] = v;
    }
}

// K4: split-K matvec; folds GAT half/head-combine + bias + relu into v load.
__global__ void __launch_bounds__(768) k_matvec(const float* __restrict__ Wfc,
                                                const float* __restrict__ b_gat) {
    int b = blockIdx.x, t = threadIdx.x;
    __shared__ float v[256];
    int k0 = b * 256;
    if (t < 256) {
        int k = k0 + t;
        float hv = 0.5f * ((g_hp[k] + g_hp[2 * KDIM + k])          // head 0
                         + (g_hp[KDIM + k] + g_hp[3 * KDIM + k]))  // head 1
                 + b_gat[t & 127];
        v[t] = fmaxf(hv, 0.f);
    }
    __syncthreads();
    const float4* W4 = (const float4*)Wfc;     // row = 768 float4
    size_t base = (size_t)k0 * 768 + t;
    float4 s0 = {0,0,0,0}, s1 = {0,0,0,0}, s2 = {0,0,0,0}, s3 = {0,0,0,0};
    #pragma unroll 2
    for (int kk = 0; kk < 256; kk += 8) {
        float4 w0 = __ldcs(&W4[base + (size_t)(kk + 0) * 768]);
        float4 w1 = __ldcs(&W4[base + (size_t)(kk + 1) * 768]);
        float4 w2 = __ldcs(&W4[base + (size_t)(kk + 2) * 768]);
        float4 w3 = __ldcs(&W4[base + (size_t)(kk + 3) * 768]);
        float4 w4 = __ldcs(&W4[base + (size_t)(kk + 4) * 768]);
        float4 w5 = __ldcs(&W4[base + (size_t)(kk + 5) * 768]);
        float4 w6 = __ldcs(&W4[base + (size_t)(kk + 6) * 768]);
        float4 w7 = __ldcs(&W4[base + (size_t)(kk + 7) * 768]);
        float v0 = v[kk], v1 = v[kk + 1], v2 = v[kk + 2], v3 = v[kk + 3];
        float v4 = v[kk + 4], v5 = v[kk + 5], v6 = v[kk + 6], v7 = v[kk + 7];
        s0.x += v0 * w0.x; s0.y += v0 * w0.y; s0.z += v0 * w0.z; s0.w += v0 * w0.w;
        s1.x += v1 * w1.x; s1.y += v1 * w1.y; s1.z += v1 * w1.z; s1.w += v1 * w1.w;
        s2.x += v2 * w2.x; s2.y += v2 * w2.y; s2.z += v2 * w2.z; s2.w += v2 * w2.w;
        s3.x += v3 * w3.x; s3.y += v3 * w3.y; s3.z += v3 * w3.z; s3.w += v3 * w3.w;
        s0.x += v4 * w4.x; s0.y += v4 * w4.y; s0.z += v4 * w4.z; s0.w += v4 * w4.w;
        s1.x += v5 * w5.x; s1.y += v5 * w5.y; s1.z += v5 * w5.z; s1.w += v5 * w5.w;
        s2.x += v6 * w6.x; s2.y += v6 * w6.y; s2.z += v6 * w6.z; s2.w += v6 * w6.w;
        s3.x += v7 * w7.x; s3.y += v7 * w7.y; s3.z += v7 * w7.z; s3.w += v7 * w7.w;
    }
    float4 r;
    r.x = s0.x + s1.x + s2.x + s3.x;
    r.y = s0.y + s1.y + s2.y + s3.y;
    r.z = s0.z + s1.z + s2.z + s3.z;
    r.w = s0.w + s1.w + s2.w + s3.w;
    ((float4*)g_part)[(size_t)b * 768 + t] = r;
}

// K5: fused reduction: 256 partials -> out, one kernel. 12 blocks x 1024.
__global__ void __launch_bounds__(1024) k_reduce(const float* __restrict__ b_fc,
                                                 float* __restrict__ out) {
    __shared__ float s[1024];
    int t = threadIdx.x;
    int o_local = t & 255, chunk = t >> 8;     // 4 chunks of 64 splits
    int o = blockIdx.x * 256 + o_local;
    float acc = 0.f;
    int s0 = chunk * 64;
    #pragma unroll 8
    for (int p = 0; p < 64; p++) acc += g_part[(size_t)(s0 + p) * OUT_DIM + o];
    s[t] = acc;
    __syncthreads();
    if (t < 256) {
        out[blockIdx.x * 256 + t] = b_fc[blockIdx.x * 256 + t]
            + ((s[t] + s[256 + t]) + (s[512 + t] + s[768 + t]));
    }
}

extern "C" void kernel_launch(void* const* d_in, const int* in_sizes, int n_in,
                              void* d_out, int out_size) {
    const float* x       = (const float*)d_in[0];
    // d_in[1] = edge_index (fully connected by construction)
    const float* W_res   = (const float*)d_in[2];
    const float* b_res   = (const float*)d_in[3];
    const float* W_rel1  = (const float*)d_in[4];
    const float* b_rel1  = (const float*)d_in[5];
    const float* W_root1 = (const float*)d_in[6];
    const float* W_rel2  = (const float*)d_in[7];
    const float* b_rel2  = (const float*)d_in[8];
    const float* W_root2 = (const float*)d_in[9];
    const float* W_gat   = (const float*)d_in[10];
    const float* att_src = (const float*)d_in[11];
    const float* att_dst = (const float*)d_in[12];
    const float* b_gat   = (const float*)d_in[13];
    const float* W_fc    = (const float*)d_in[14];
    const float* b_fc    = (const float*)d_in[15];
    float* out = (float*)d_out;

    k_h1<<<128, 128>>>(x, W_res, b_res, W_rel1, b_rel1, W_root1);
    k_h2xh<<<128, 512>>>(W_rel2, W_root2, b_rel2, W_gat, att_src, att_dst);
    k_gat<<<256, 256>>>();
    k_matvec<<<KSPLITS, 768>>>(W_fc, b_gat);
    k_reduce<<<12, 1024>>>(b_fc, out);
}